// round 2
// baseline (speedup 1.0000x reference)
#include <cuda_runtime.h>
#include <cstdint>

#define N_NODES 100000
#define IN_DIM  768
#define OUT_DIM 128

// -------- scratch (device globals; no allocation allowed) --------
__device__ float d_h[(size_t)N_NODES * OUT_DIM];     // (features@Wd + bd) * norm_src
__device__ float d_agg[(size_t)N_NODES * OUT_DIM];   // scatter-sum target
__device__ float d_norm_src[N_NODES];                // counts -> rsqrt
__device__ float d_norm_dst[N_NODES];
__device__ float d_Wc[OUT_DIM * IN_DIM];             // Wg @ Wu   [128,768]
__device__ float d_bc[IN_DIM];                       // bg @ Wu + bu

// -------- zero counts + agg --------
__global__ void zero_kernel(int n_nodes) {
    size_t i = (size_t)blockIdx.x * blockDim.x + threadIdx.x;
    size_t total = (size_t)n_nodes * OUT_DIM;
    for (size_t idx = i; idx < total; idx += (size_t)gridDim.x * blockDim.x) {
        d_agg[idx] = 0.0f;
        if (idx < (size_t)n_nodes) { d_norm_src[idx] = 0.0f; d_norm_dst[idx] = 0.0f; }
    }
}

// -------- degree counting --------
__global__ void degree_kernel(const int* __restrict__ src, const int* __restrict__ dst, int n_edges) {
    int i = blockIdx.x * blockDim.x + threadIdx.x;
    if (i < n_edges) {
        atomicAdd(&d_norm_src[src[i]], 1.0f);
        atomicAdd(&d_norm_dst[dst[i]], 1.0f);
    }
}

__global__ void norm_finalize_kernel(int n_nodes) {
    int i = blockIdx.x * blockDim.x + threadIdx.x;
    if (i < n_nodes) {
        d_norm_src[i] = rsqrtf(fmaxf(d_norm_src[i], 1.0f));
        d_norm_dst[i] = rsqrtf(fmaxf(d_norm_dst[i], 1.0f));
    }
}

// -------- Wc = Wg @ Wu ; bc = bg @ Wu + bu --------
__global__ void combine_w_kernel(const float* __restrict__ Wg, const float* __restrict__ bg,
                                 const float* __restrict__ Wu, const float* __restrict__ bu) {
    int idx = blockIdx.x * blockDim.x + threadIdx.x;   // over 128*768
    if (idx < OUT_DIM * IN_DIM) {
        int i = idx / IN_DIM;   // row in Wg
        int j = idx % IN_DIM;   // col in Wu
        float acc = 0.0f;
        #pragma unroll 8
        for (int k = 0; k < OUT_DIM; k++)
            acc += Wg[i * OUT_DIM + k] * Wu[k * IN_DIM + j];
        d_Wc[idx] = acc;
    }
    if (idx < IN_DIM) {
        float acc = bu[idx];
        #pragma unroll 8
        for (int k = 0; k < OUT_DIM; k++)
            acc += bg[k] * Wu[k * IN_DIM + idx];
        d_bc[idx] = acc;
    }
}

// -------- SGEMM: C[M,N] = epilogue(A@B)  --------
// SCALE_AFTER_BIAS:  C = (acc + bias[n]) * rowscale[m]      (GEMM1)
// !SCALE_AFTER_BIAS: C = acc * rowscale[m] + bias[n]        (GEMM2)
// BM=64, BN=64, BK=16, 256 threads, 4x4 per thread.
template<int BM, int BN, int BK, int TM, int TN, bool SCALE_AFTER_BIAS>
__global__ void sgemm_rowscale_bias(const float* __restrict__ A,
                                    const float* __restrict__ B,
                                    const float* __restrict__ bias,
                                    const float* __restrict__ rowscale,
                                    float* __restrict__ C,
                                    int M, int N, int K) {
    __shared__ float As[BK][BM];       // transposed A tile
    __shared__ float Bs[BK][BN];

    const int tid = threadIdx.x;       // 256
    const int block_row = blockIdx.y * BM;
    const int block_col = blockIdx.x * BN;

    const int tr = tid / (BN / TN);    // 0..15
    const int tc = tid % (BN / TN);    // 0..15

    // A tile loads: 64 rows x 16 k, one float4 per thread (4 threads per row)
    const int a_row  = tid >> 2;            // 0..63
    const int a_col4 = (tid & 3) << 2;      // 0,4,8,12
    // B tile loads: 16 k-rows x 64 cols, one float4 per thread
    const int b_row  = tid / (BN / 4);      // 0..15
    const int b_col4 = (tid % (BN / 4)) * 4;

    float acc[TM][TN] = {};

    for (int k0 = 0; k0 < K; k0 += BK) {
        const int gr = block_row + a_row;
        float4 av = make_float4(0.f, 0.f, 0.f, 0.f);
        if (gr < M)
            av = *reinterpret_cast<const float4*>(A + (size_t)gr * K + k0 + a_col4);
        As[a_col4 + 0][a_row] = av.x;
        As[a_col4 + 1][a_row] = av.y;
        As[a_col4 + 2][a_row] = av.z;
        As[a_col4 + 3][a_row] = av.w;

        float4 bv = *reinterpret_cast<const float4*>(B + (size_t)(k0 + b_row) * N + block_col + b_col4);
        *reinterpret_cast<float4*>(&Bs[b_row][b_col4]) = bv;

        __syncthreads();

        #pragma unroll
        for (int k = 0; k < BK; k++) {
            float ar[TM], br[TN];
            #pragma unroll
            for (int i = 0; i < TM; i++) ar[i] = As[k][tr * TM + i];
            #pragma unroll
            for (int j = 0; j < TN; j++) br[j] = Bs[k][tc * TN + j];
            #pragma unroll
            for (int i = 0; i < TM; i++)
                #pragma unroll
                for (int j = 0; j < TN; j++)
                    acc[i][j] += ar[i] * br[j];
        }
        __syncthreads();
    }

    #pragma unroll
    for (int i = 0; i < TM; i++) {
        const int r = block_row + tr * TM + i;
        if (r >= M) continue;
        const float s = rowscale[r];
        #pragma unroll
        for (int j = 0; j < TN; j += 4) {
            const int c = block_col + tc * TN + j;
            float4 o;
            if (SCALE_AFTER_BIAS) {
                o.x = (acc[i][j + 0] + bias[c + 0]) * s;
                o.y = (acc[i][j + 1] + bias[c + 1]) * s;
                o.z = (acc[i][j + 2] + bias[c + 2]) * s;
                o.w = (acc[i][j + 3] + bias[c + 3]) * s;
            } else {
                o.x = fmaf(acc[i][j + 0], s, bias[c + 0]);
                o.y = fmaf(acc[i][j + 1], s, bias[c + 1]);
                o.z = fmaf(acc[i][j + 2], s, bias[c + 2]);
                o.w = fmaf(acc[i][j + 3], s, bias[c + 3]);
            }
            *reinterpret_cast<float4*>(C + (size_t)r * N + c) = o;
        }
    }
}

// -------- edge scatter: agg[dst] += h[src], one warp per edge --------
__global__ void scatter_kernel(const int* __restrict__ src, const int* __restrict__ dst, int n_edges) {
    const int warps_per_block = blockDim.x >> 5;
    const int e = blockIdx.x * warps_per_block + (threadIdx.x >> 5);
    const int lane = threadIdx.x & 31;
    if (e >= n_edges) return;
    const int s = __ldg(src + e);
    const int d = __ldg(dst + e);
    const float4 v = reinterpret_cast<const float4*>(d_h + (size_t)s * OUT_DIM)[lane];
    float* ap = d_agg + (size_t)d * OUT_DIM + lane * 4;
    atomicAdd(ap + 0, v.x);
    atomicAdd(ap + 1, v.y);
    atomicAdd(ap + 2, v.z);
    atomicAdd(ap + 3, v.w);
}

extern "C" void kernel_launch(void* const* d_in, const int* in_sizes, int n_in,
                              void* d_out, int out_size) {
    const float* features = (const float*)d_in[0];   // [N, 768]
    const float* Wd       = (const float*)d_in[1];   // [768, 128]
    const float* bd       = (const float*)d_in[2];   // [128]
    const float* Wg       = (const float*)d_in[3];   // [128, 128]
    const float* bg       = (const float*)d_in[4];   // [128]
    const float* Wu       = (const float*)d_in[5];   // [128, 768]
    const float* bu       = (const float*)d_in[6];   // [768]
    const int*   src      = (const int*)d_in[7];     // [E]
    const int*   dst      = (const int*)d_in[8];     // [E]
    float*       out      = (float*)d_out;           // [N, 768]

    const int n_nodes = in_sizes[0] / IN_DIM;
    const int n_edges = in_sizes[7];

    // resolve scratch symbol addresses (host-side, not stream ops; capture-safe)
    static float* p_h = nullptr; static float* p_agg = nullptr;
    static float* p_ns = nullptr; static float* p_nd = nullptr;
    static float* p_Wc = nullptr; static float* p_bc = nullptr;
    if (!p_h) {
        cudaGetSymbolAddress((void**)&p_h,  d_h);
        cudaGetSymbolAddress((void**)&p_agg, d_agg);
        cudaGetSymbolAddress((void**)&p_ns, d_norm_src);
        cudaGetSymbolAddress((void**)&p_nd, d_norm_dst);
        cudaGetSymbolAddress((void**)&p_Wc, d_Wc);
        cudaGetSymbolAddress((void**)&p_bc, d_bc);
    }

    // 1) zero counters + agg
    zero_kernel<<<1024, 256>>>(n_nodes);

    // 2) degrees
    degree_kernel<<<(n_edges + 255) / 256, 256>>>(src, dst, n_edges);

    // 3) norms
    norm_finalize_kernel<<<(n_nodes + 255) / 256, 256>>>(n_nodes);

    // 4) h = (features @ Wd + bd) * norm_src   [N,128]
    {
        dim3 grid(OUT_DIM / 64, (n_nodes + 63) / 64);
        sgemm_rowscale_bias<64, 64, 16, 4, 4, true><<<grid, 256>>>(
            features, Wd, bd, p_ns, p_h, n_nodes, OUT_DIM, IN_DIM);
    }

    // 5) Wc = Wg@Wu, bc = bg@Wu + bu
    combine_w_kernel<<<(OUT_DIM * IN_DIM + 255) / 256, 256>>>(Wg, bg, Wu, bu);

    // 6) scatter: agg[dst] += h[src]
    {
        const int warps_per_block = 8;
        const int threads = warps_per_block * 32;
        scatter_kernel<<<(n_edges + warps_per_block - 1) / warps_per_block, threads>>>(src, dst, n_edges);
    }

    // 7) out = (agg @ Wc) * norm_dst + bc     [N,768]
    {
        dim3 grid(IN_DIM / 64, (n_nodes + 63) / 64);
        sgemm_rowscale_bias<64, 64, 16, 4, 4, false><<<grid, 256>>>(
            p_agg, p_Wc, p_bc, p_nd, out, n_nodes, IN_DIM, OUT_DIM);
    }
}

// round 3
// speedup vs baseline: 1.3969x; 1.3969x over previous
#include <cuda_runtime.h>
#include <cstdint>

#define N_NODES 100000
#define IN_DIM  768
#define OUT_DIM 128
#define MAX_EDGES 1600000

// -------- scratch (device globals; no allocation allowed) --------
__device__ float d_h[(size_t)N_NODES * OUT_DIM];     // (features@Wd + bd) * norm_src
__device__ float d_agg[(size_t)N_NODES * OUT_DIM];   // gather target
__device__ float d_norm_src[N_NODES];
__device__ float d_norm_dst[N_NODES];
__device__ float d_Wc[OUT_DIM * IN_DIM];             // Wg @ Wu   [128,768]
__device__ float d_bc[IN_DIM];                       // bg @ Wu + bu
__device__ int   d_outdeg[N_NODES];
__device__ int   d_indeg[N_NODES];
__device__ int   d_off[N_NODES + 1];
__device__ int   d_cursor[N_NODES];
__device__ int   d_blocksums[(N_NODES + 1023) / 1024 + 1];
__device__ int   d_edge_src[MAX_EDGES];

// -------- zero degree counters --------
__global__ void zero_deg_kernel(int n_nodes) {
    int i = blockIdx.x * blockDim.x + threadIdx.x;
    if (i < n_nodes) { d_outdeg[i] = 0; d_indeg[i] = 0; }
}

// -------- degree counting (int) --------
__global__ void degree_kernel(const int* __restrict__ src, const int* __restrict__ dst, int n_edges) {
    int i = blockIdx.x * blockDim.x + threadIdx.x;
    if (i < n_edges) {
        atomicAdd(&d_outdeg[src[i]], 1);
        atomicAdd(&d_indeg[dst[i]], 1);
    }
}

__global__ void norm_finalize_kernel(int n_nodes) {
    int i = blockIdx.x * blockDim.x + threadIdx.x;
    if (i < n_nodes) {
        d_norm_src[i] = rsqrtf(fmaxf((float)d_outdeg[i], 1.0f));
        d_norm_dst[i] = rsqrtf(fmaxf((float)d_indeg[i], 1.0f));
    }
}

// -------- exclusive scan of indeg -> d_off (3-phase) --------
__global__ void scan_block_kernel(int n) {
    __shared__ int sh[1024];
    int gid = blockIdx.x * 1024 + threadIdx.x;
    int v = (gid < n) ? d_indeg[gid] : 0;
    sh[threadIdx.x] = v;
    __syncthreads();
    #pragma unroll
    for (int d = 1; d < 1024; d <<= 1) {
        int t = (threadIdx.x >= d) ? sh[threadIdx.x - d] : 0;
        __syncthreads();
        sh[threadIdx.x] += t;
        __syncthreads();
    }
    if (gid < n) d_off[gid] = sh[threadIdx.x] - v;   // exclusive
    if (threadIdx.x == 1023) d_blocksums[blockIdx.x] = sh[1023];
}

__global__ void scan_sums_kernel(int nb) {
    if (threadIdx.x == 0 && blockIdx.x == 0) {
        int acc = 0;
        for (int i = 0; i < nb; i++) { int v = d_blocksums[i]; d_blocksums[i] = acc; acc += v; }
    }
}

__global__ void scan_add_kernel(int n) {
    int gid = blockIdx.x * blockDim.x + threadIdx.x;
    if (gid < n) {
        d_off[gid] += d_blocksums[gid >> 10];
        d_cursor[gid] = 0;
    }
}

// -------- CSR fill: edge list sorted by dst --------
__global__ void csr_fill_kernel(const int* __restrict__ src, const int* __restrict__ dst, int n_edges) {
    int e = blockIdx.x * blockDim.x + threadIdx.x;
    if (e < n_edges) {
        int d = dst[e];
        int pos = d_off[d] + atomicAdd(&d_cursor[d], 1);
        d_edge_src[pos] = src[e];
    }
}

// -------- gather: agg[v] = sum_{e: dst=v} h[src[e]]   (one warp per node) --------
__global__ void gather_kernel(int n_nodes) {
    const int node = blockIdx.x * (blockDim.x >> 5) + (threadIdx.x >> 5);
    const int lane = threadIdx.x & 31;
    if (node >= n_nodes) return;
    const int beg = d_off[node];
    const int cnt = d_indeg[node];

    float4 acc = make_float4(0.f, 0.f, 0.f, 0.f);
    int j = 0;
    for (; j + 4 <= cnt; j += 4) {
        const int s0 = d_edge_src[beg + j + 0];
        const int s1 = d_edge_src[beg + j + 1];
        const int s2 = d_edge_src[beg + j + 2];
        const int s3 = d_edge_src[beg + j + 3];
        float4 v0 = reinterpret_cast<const float4*>(d_h + (size_t)s0 * OUT_DIM)[lane];
        float4 v1 = reinterpret_cast<const float4*>(d_h + (size_t)s1 * OUT_DIM)[lane];
        float4 v2 = reinterpret_cast<const float4*>(d_h + (size_t)s2 * OUT_DIM)[lane];
        float4 v3 = reinterpret_cast<const float4*>(d_h + (size_t)s3 * OUT_DIM)[lane];
        acc.x += v0.x + v1.x + v2.x + v3.x;
        acc.y += v0.y + v1.y + v2.y + v3.y;
        acc.z += v0.z + v1.z + v2.z + v3.z;
        acc.w += v0.w + v1.w + v2.w + v3.w;
    }
    for (; j < cnt; j++) {
        const int s = d_edge_src[beg + j];
        float4 v = reinterpret_cast<const float4*>(d_h + (size_t)s * OUT_DIM)[lane];
        acc.x += v.x; acc.y += v.y; acc.z += v.z; acc.w += v.w;
    }
    reinterpret_cast<float4*>(d_agg + (size_t)node * OUT_DIM)[lane] = acc;
}

// -------- Wc = Wg @ Wu ; bc = bg @ Wu + bu --------
__global__ void combine_w_kernel(const float* __restrict__ Wg, const float* __restrict__ bg,
                                 const float* __restrict__ Wu, const float* __restrict__ bu) {
    int idx = blockIdx.x * blockDim.x + threadIdx.x;
    if (idx < OUT_DIM * IN_DIM) {
        int i = idx / IN_DIM;
        int j = idx % IN_DIM;
        float acc = 0.0f;
        #pragma unroll 8
        for (int k = 0; k < OUT_DIM; k++)
            acc += Wg[i * OUT_DIM + k] * Wu[k * IN_DIM + j];
        d_Wc[idx] = acc;
    }
    if (idx < IN_DIM) {
        float acc = bu[idx];
        #pragma unroll 8
        for (int k = 0; k < OUT_DIM; k++)
            acc += bg[k] * Wu[k * IN_DIM + idx];
        d_bc[idx] = acc;
    }
}

// -------- SGEMM 128x128x8, 8x8/thread, 256 threads --------
// SCALE_AFTER_BIAS:  C = (acc + bias[n]) * rowscale[m]      (GEMM1)
// !SCALE_AFTER_BIAS: C = acc * rowscale[m] + bias[n]        (GEMM2)
template<bool SCALE_AFTER_BIAS>
__global__ __launch_bounds__(256, 2)
void sgemm128(const float* __restrict__ A, const float* __restrict__ B,
              const float* __restrict__ bias, const float* __restrict__ rowscale,
              float* __restrict__ C, int M, int N, int K) {
    __shared__ float As[8][128];
    __shared__ float Bs[8][128];

    const int tid = threadIdx.x;
    const int brow = blockIdx.y * 128;
    const int bcol = blockIdx.x * 128;

    const int tr = (tid / 16) * 8;        // 0..120 step 8
    const int tc = (tid % 16) * 8;

    const int a_row = tid >> 1;           // 0..127
    const int a_col = (tid & 1) * 4;      // 0 or 4
    const int b_row = tid >> 5;           // 0..7
    const int b_col = (tid & 31) * 4;     // 0..124 step 4

    float acc[8][8] = {};

    for (int k0 = 0; k0 < K; k0 += 8) {
        const int gr = brow + a_row;
        float4 av = make_float4(0.f, 0.f, 0.f, 0.f);
        if (gr < M)
            av = *reinterpret_cast<const float4*>(A + (size_t)gr * K + k0 + a_col);
        As[a_col + 0][a_row] = av.x;
        As[a_col + 1][a_row] = av.y;
        As[a_col + 2][a_row] = av.z;
        As[a_col + 3][a_row] = av.w;

        float4 bv = *reinterpret_cast<const float4*>(B + (size_t)(k0 + b_row) * N + bcol + b_col);
        *reinterpret_cast<float4*>(&Bs[b_row][b_col]) = bv;

        __syncthreads();

        #pragma unroll
        for (int k = 0; k < 8; k++) {
            float ar[8], br[8];
            *reinterpret_cast<float4*>(ar)     = *reinterpret_cast<const float4*>(&As[k][tr]);
            *reinterpret_cast<float4*>(ar + 4) = *reinterpret_cast<const float4*>(&As[k][tr + 4]);
            *reinterpret_cast<float4*>(br)     = *reinterpret_cast<const float4*>(&Bs[k][tc]);
            *reinterpret_cast<float4*>(br + 4) = *reinterpret_cast<const float4*>(&Bs[k][tc + 4]);
            #pragma unroll
            for (int i = 0; i < 8; i++)
                #pragma unroll
                for (int jj = 0; jj < 8; jj++)
                    acc[i][jj] = fmaf(ar[i], br[jj], acc[i][jj]);
        }
        __syncthreads();
    }

    #pragma unroll
    for (int i = 0; i < 8; i++) {
        const int r = brow + tr + i;
        if (r >= M) continue;
        const float s = rowscale[r];
        #pragma unroll
        for (int jj = 0; jj < 8; jj += 4) {
            const int c = bcol + tc + jj;
            float4 o;
            if (SCALE_AFTER_BIAS) {
                o.x = (acc[i][jj + 0] + bias[c + 0]) * s;
                o.y = (acc[i][jj + 1] + bias[c + 1]) * s;
                o.z = (acc[i][jj + 2] + bias[c + 2]) * s;
                o.w = (acc[i][jj + 3] + bias[c + 3]) * s;
            } else {
                o.x = fmaf(acc[i][jj + 0], s, bias[c + 0]);
                o.y = fmaf(acc[i][jj + 1], s, bias[c + 1]);
                o.z = fmaf(acc[i][jj + 2], s, bias[c + 2]);
                o.w = fmaf(acc[i][jj + 3], s, bias[c + 3]);
            }
            *reinterpret_cast<float4*>(C + (size_t)r * N + c) = o;
        }
    }
}

extern "C" void kernel_launch(void* const* d_in, const int* in_sizes, int n_in,
                              void* d_out, int out_size) {
    const float* features = (const float*)d_in[0];   // [N, 768]
    const float* Wd       = (const float*)d_in[1];   // [768, 128]
    const float* bd       = (const float*)d_in[2];   // [128]
    const float* Wg       = (const float*)d_in[3];   // [128, 128]
    const float* bg       = (const float*)d_in[4];   // [128]
    const float* Wu       = (const float*)d_in[5];   // [128, 768]
    const float* bu       = (const float*)d_in[6];   // [768]
    const int*   src      = (const int*)d_in[7];     // [E]
    const int*   dst      = (const int*)d_in[8];     // [E]
    float*       out      = (float*)d_out;           // [N, 768]

    const int n_nodes = in_sizes[0] / IN_DIM;
    const int n_edges = in_sizes[7];

    static float* p_h = nullptr; static float* p_agg = nullptr;
    static float* p_ns = nullptr; static float* p_nd = nullptr;
    static float* p_Wc = nullptr; static float* p_bc = nullptr;
    if (!p_h) {
        cudaGetSymbolAddress((void**)&p_h,   d_h);
        cudaGetSymbolAddress((void**)&p_agg, d_agg);
        cudaGetSymbolAddress((void**)&p_ns,  d_norm_src);
        cudaGetSymbolAddress((void**)&p_nd,  d_norm_dst);
        cudaGetSymbolAddress((void**)&p_Wc,  d_Wc);
        cudaGetSymbolAddress((void**)&p_bc,  d_bc);
    }

    const int nscan_blocks = (n_nodes + 1023) / 1024;

    // 1) zero degree counters
    zero_deg_kernel<<<(n_nodes + 255) / 256, 256>>>(n_nodes);

    // 2) degrees
    degree_kernel<<<(n_edges + 255) / 256, 256>>>(src, dst, n_edges);

    // 3) norms
    norm_finalize_kernel<<<(n_nodes + 255) / 256, 256>>>(n_nodes);

    // 4) exclusive scan of indeg -> off, zero cursors
    scan_block_kernel<<<nscan_blocks, 1024>>>(n_nodes);
    scan_sums_kernel<<<1, 32>>>(nscan_blocks);
    scan_add_kernel<<<(n_nodes + 255) / 256, 256>>>(n_nodes);

    // 5) CSR fill (sorted-by-dst edge source list)
    csr_fill_kernel<<<(n_edges + 255) / 256, 256>>>(src, dst, n_edges);

    // 6) h = (features @ Wd + bd) * norm_src   [N,128]
    {
        dim3 grid(OUT_DIM / 128, (n_nodes + 127) / 128);
        sgemm128<true><<<grid, 256>>>(features, Wd, bd, p_ns, p_h, n_nodes, OUT_DIM, IN_DIM);
    }

    // 7) Wc = Wg@Wu, bc = bg@Wu + bu
    combine_w_kernel<<<(OUT_DIM * IN_DIM + 255) / 256, 256>>>(Wg, bg, Wu, bu);

    // 8) gather: agg[v] = sum h[src] over in-edges (no atomics)
    gather_kernel<<<(n_nodes + 7) / 8, 256>>>(n_nodes);

    // 9) out = (agg @ Wc) * norm_dst + bc     [N,768]
    {
        dim3 grid(IN_DIM / 128, (n_nodes + 127) / 128);
        sgemm128<false><<<grid, 256>>>(p_agg, p_Wc, p_bc, p_nd, out, n_nodes, IN_DIM, OUT_DIM);
    }
}

// round 4
// speedup vs baseline: 2.8483x; 2.0390x over previous
#include <cuda_runtime.h>
#include <cstdint>

#define N_NODES 100000
#define IN_DIM  768
#define OUT_DIM 128
#define MAX_EDGES 1600000

// -------- scratch (device globals; no allocation allowed) --------
__device__ float d_h[(size_t)N_NODES * OUT_DIM];
__device__ float d_agg[(size_t)N_NODES * OUT_DIM];
__device__ float d_norm_src[N_NODES];
__device__ float d_norm_dst[N_NODES];
__device__ float d_Wc[OUT_DIM * IN_DIM];             // Wg @ Wu   [128,768]
__device__ float d_bc[IN_DIM];                       // bg @ Wu + bu
__device__ int   d_outdeg[N_NODES];
__device__ int   d_indeg[N_NODES];
__device__ int   d_off[N_NODES + 1];
__device__ int   d_cursor[N_NODES];
__device__ int   d_blocksums[(N_NODES + 1023) / 1024 + 1];
__device__ int   d_edge_src[MAX_EDGES];

__device__ __forceinline__ uint32_t f2tf32(float f) {
    uint32_t u;
    asm("cvt.rna.tf32.f32 %0, %1;" : "=r"(u) : "f"(f));
    return u;
}

// -------- zero degree counters --------
__global__ void zero_deg_kernel(int n_nodes) {
    int i = blockIdx.x * blockDim.x + threadIdx.x;
    if (i < n_nodes) { d_outdeg[i] = 0; d_indeg[i] = 0; }
}

__global__ void degree_kernel(const int* __restrict__ src, const int* __restrict__ dst, int n_edges) {
    int i = blockIdx.x * blockDim.x + threadIdx.x;
    if (i < n_edges) {
        atomicAdd(&d_outdeg[src[i]], 1);
        atomicAdd(&d_indeg[dst[i]], 1);
    }
}

__global__ void norm_finalize_kernel(int n_nodes) {
    int i = blockIdx.x * blockDim.x + threadIdx.x;
    if (i < n_nodes) {
        d_norm_src[i] = rsqrtf(fmaxf((float)d_outdeg[i], 1.0f));
        d_norm_dst[i] = rsqrtf(fmaxf((float)d_indeg[i], 1.0f));
    }
}

// -------- exclusive scan of indeg -> d_off --------
__global__ void scan_block_kernel(int n) {
    __shared__ int sh[1024];
    int gid = blockIdx.x * 1024 + threadIdx.x;
    int v = (gid < n) ? d_indeg[gid] : 0;
    sh[threadIdx.x] = v;
    __syncthreads();
    #pragma unroll
    for (int d = 1; d < 1024; d <<= 1) {
        int t = (threadIdx.x >= d) ? sh[threadIdx.x - d] : 0;
        __syncthreads();
        sh[threadIdx.x] += t;
        __syncthreads();
    }
    if (gid < n) d_off[gid] = sh[threadIdx.x] - v;
    if (threadIdx.x == 1023) d_blocksums[blockIdx.x] = sh[1023];
}

__global__ void scan_sums_kernel(int nb) {
    if (threadIdx.x == 0 && blockIdx.x == 0) {
        int acc = 0;
        for (int i = 0; i < nb; i++) { int v = d_blocksums[i]; d_blocksums[i] = acc; acc += v; }
    }
}

__global__ void scan_add_kernel(int n) {
    int gid = blockIdx.x * blockDim.x + threadIdx.x;
    if (gid < n) {
        d_off[gid] += d_blocksums[gid >> 10];
        d_cursor[gid] = 0;
    }
}

__global__ void csr_fill_kernel(const int* __restrict__ src, const int* __restrict__ dst, int n_edges) {
    int e = blockIdx.x * blockDim.x + threadIdx.x;
    if (e < n_edges) {
        int d = dst[e];
        int pos = d_off[d] + atomicAdd(&d_cursor[d], 1);
        d_edge_src[pos] = src[e];
    }
}

// -------- gather: agg[v] = sum_{e: dst=v} h[src[e]]  (one warp per node) --------
__global__ void gather_kernel(int n_nodes) {
    const int node = blockIdx.x * (blockDim.x >> 5) + (threadIdx.x >> 5);
    const int lane = threadIdx.x & 31;
    if (node >= n_nodes) return;
    const int beg = d_off[node];
    const int cnt = d_indeg[node];

    float4 acc = make_float4(0.f, 0.f, 0.f, 0.f);
    int j = 0;
    for (; j + 4 <= cnt; j += 4) {
        const int s0 = d_edge_src[beg + j + 0];
        const int s1 = d_edge_src[beg + j + 1];
        const int s2 = d_edge_src[beg + j + 2];
        const int s3 = d_edge_src[beg + j + 3];
        float4 v0 = reinterpret_cast<const float4*>(d_h + (size_t)s0 * OUT_DIM)[lane];
        float4 v1 = reinterpret_cast<const float4*>(d_h + (size_t)s1 * OUT_DIM)[lane];
        float4 v2 = reinterpret_cast<const float4*>(d_h + (size_t)s2 * OUT_DIM)[lane];
        float4 v3 = reinterpret_cast<const float4*>(d_h + (size_t)s3 * OUT_DIM)[lane];
        acc.x += v0.x + v1.x + v2.x + v3.x;
        acc.y += v0.y + v1.y + v2.y + v3.y;
        acc.z += v0.z + v1.z + v2.z + v3.z;
        acc.w += v0.w + v1.w + v2.w + v3.w;
    }
    for (; j < cnt; j++) {
        const int s = d_edge_src[beg + j];
        float4 v = reinterpret_cast<const float4*>(d_h + (size_t)s * OUT_DIM)[lane];
        acc.x += v.x; acc.y += v.y; acc.z += v.z; acc.w += v.w;
    }
    reinterpret_cast<float4*>(d_agg + (size_t)node * OUT_DIM)[lane] = acc;
}

// -------- Wc = Wg @ Wu ; bc = bg @ Wu + bu --------
__global__ void combine_w_kernel(const float* __restrict__ Wg, const float* __restrict__ bg,
                                 const float* __restrict__ Wu, const float* __restrict__ bu) {
    int idx = blockIdx.x * blockDim.x + threadIdx.x;
    if (idx < OUT_DIM * IN_DIM) {
        int i = idx / IN_DIM;
        int j = idx % IN_DIM;
        float acc = 0.0f;
        #pragma unroll 8
        for (int k = 0; k < OUT_DIM; k++)
            acc += Wg[i * OUT_DIM + k] * Wu[k * IN_DIM + j];
        d_Wc[idx] = acc;
    }
    if (idx < IN_DIM) {
        float acc = bu[idx];
        #pragma unroll 8
        for (int k = 0; k < OUT_DIM; k++)
            acc += bg[k] * Wu[k * IN_DIM + idx];
        d_bc[idx] = acc;
    }
}

// ================= TF32 tensor-core GEMM =================
// C[M,N] = epilogue(A[M,K] @ B[K,N])
// Block 128x128x16, 256 threads (8 warps, 2x4), warp tile 64x32.
// mma.sync.aligned.m16n8k8.row.col.f32.tf32.tf32.f32
#define SMEM_STRIDE 136   // 128 + 8 pad: conflict-free fragment LDS

template<bool SCALE_AFTER_BIAS>
__global__ __launch_bounds__(256, 2)
void tf32_gemm(const float* __restrict__ A, const float* __restrict__ B,
               const float* __restrict__ bias, const float* __restrict__ rowscale,
               float* __restrict__ C, int M, int N, int K) {
    __shared__ float As[16 * SMEM_STRIDE];   // [k][m] transposed
    __shared__ float Bs[16 * SMEM_STRIDE];   // [k][n]

    const int tid  = threadIdx.x;
    const int lane = tid & 31;
    const int wid  = tid >> 5;
    const int warp_m = (wid >> 2) * 64;   // 0 or 64
    const int warp_n = (wid & 3) * 32;    // 0,32,64,96

    const int brow = blockIdx.y * 128;
    const int bcol = blockIdx.x * 128;

    const int grp = lane >> 2;   // 0..7
    const int tig = lane & 3;    // 0..3

    float acc[4][4][4];
    #pragma unroll
    for (int a = 0; a < 4; a++)
        #pragma unroll
        for (int b = 0; b < 4; b++)
            #pragma unroll
            for (int c = 0; c < 4; c++) acc[a][b][c] = 0.f;

    for (int k0 = 0; k0 < K; k0 += 16) {
        // ---- load A tile: 128 rows x 16 k ----
        #pragma unroll
        for (int l = 0; l < 2; l++) {
            const int idx  = tid + l * 256;
            const int arow = idx >> 2;
            const int acol = (idx & 3) << 2;
            const int gr = brow + arow;
            float4 av = make_float4(0.f, 0.f, 0.f, 0.f);
            if (gr < M)
                av = *reinterpret_cast<const float4*>(A + (size_t)gr * K + k0 + acol);
            As[(acol + 0) * SMEM_STRIDE + arow] = __uint_as_float(f2tf32(av.x));
            As[(acol + 1) * SMEM_STRIDE + arow] = __uint_as_float(f2tf32(av.y));
            As[(acol + 2) * SMEM_STRIDE + arow] = __uint_as_float(f2tf32(av.z));
            As[(acol + 3) * SMEM_STRIDE + arow] = __uint_as_float(f2tf32(av.w));
        }
        // ---- load B tile: 16 k x 128 n ----
        #pragma unroll
        for (int l = 0; l < 2; l++) {
            const int idx  = tid + l * 256;
            const int krow = idx >> 5;
            const int ncol = (idx & 31) << 2;
            float4 bv = *reinterpret_cast<const float4*>(B + (size_t)(k0 + krow) * N + bcol + ncol);
            float4 cv;
            cv.x = __uint_as_float(f2tf32(bv.x));
            cv.y = __uint_as_float(f2tf32(bv.y));
            cv.z = __uint_as_float(f2tf32(bv.z));
            cv.w = __uint_as_float(f2tf32(bv.w));
            *reinterpret_cast<float4*>(&Bs[krow * SMEM_STRIDE + ncol]) = cv;
        }
        __syncthreads();

        #pragma unroll
        for (int kk = 0; kk < 16; kk += 8) {
            uint32_t afr[4][4];
            #pragma unroll
            for (int mt = 0; mt < 4; mt++) {
                const int m0 = warp_m + mt * 16;
                afr[mt][0] = __float_as_uint(As[(kk + tig    ) * SMEM_STRIDE + m0 + grp    ]);
                afr[mt][1] = __float_as_uint(As[(kk + tig    ) * SMEM_STRIDE + m0 + grp + 8]);
                afr[mt][2] = __float_as_uint(As[(kk + tig + 4) * SMEM_STRIDE + m0 + grp    ]);
                afr[mt][3] = __float_as_uint(As[(kk + tig + 4) * SMEM_STRIDE + m0 + grp + 8]);
            }
            uint32_t bfr[4][2];
            #pragma unroll
            for (int nt = 0; nt < 4; nt++) {
                const int n0 = warp_n + nt * 8;
                bfr[nt][0] = __float_as_uint(Bs[(kk + tig    ) * SMEM_STRIDE + n0 + grp]);
                bfr[nt][1] = __float_as_uint(Bs[(kk + tig + 4) * SMEM_STRIDE + n0 + grp]);
            }
            #pragma unroll
            for (int mt = 0; mt < 4; mt++)
                #pragma unroll
                for (int nt = 0; nt < 4; nt++) {
                    asm volatile(
                        "mma.sync.aligned.m16n8k8.row.col.f32.tf32.tf32.f32 "
                        "{%0,%1,%2,%3}, {%4,%5,%6,%7}, {%8,%9}, {%0,%1,%2,%3};"
                        : "+f"(acc[mt][nt][0]), "+f"(acc[mt][nt][1]),
                          "+f"(acc[mt][nt][2]), "+f"(acc[mt][nt][3])
                        : "r"(afr[mt][0]), "r"(afr[mt][1]), "r"(afr[mt][2]), "r"(afr[mt][3]),
                          "r"(bfr[nt][0]), "r"(bfr[nt][1]));
                }
        }
        __syncthreads();
    }

    // ---- epilogue ----
    #pragma unroll
    for (int mt = 0; mt < 4; mt++) {
        const int r0 = brow + warp_m + mt * 16 + grp;
        const int r1 = r0 + 8;
        const bool ok0 = (r0 < M);
        const bool ok1 = (r1 < M);
        const float s0 = ok0 ? rowscale[r0] : 0.f;
        const float s1 = ok1 ? rowscale[r1] : 0.f;
        #pragma unroll
        for (int nt = 0; nt < 4; nt++) {
            const int c = bcol + warp_n + nt * 8 + 2 * tig;
            const float bz0 = bias[c], bz1 = bias[c + 1];
            if (ok0) {
                float2 o;
                if (SCALE_AFTER_BIAS) {
                    o.x = (acc[mt][nt][0] + bz0) * s0;
                    o.y = (acc[mt][nt][1] + bz1) * s0;
                } else {
                    o.x = fmaf(acc[mt][nt][0], s0, bz0);
                    o.y = fmaf(acc[mt][nt][1], s0, bz1);
                }
                *reinterpret_cast<float2*>(C + (size_t)r0 * N + c) = o;
            }
            if (ok1) {
                float2 o;
                if (SCALE_AFTER_BIAS) {
                    o.x = (acc[mt][nt][2] + bz0) * s1;
                    o.y = (acc[mt][nt][3] + bz1) * s1;
                } else {
                    o.x = fmaf(acc[mt][nt][2], s1, bz0);
                    o.y = fmaf(acc[mt][nt][3], s1, bz1);
                }
                *reinterpret_cast<float2*>(C + (size_t)r1 * N + c) = o;
            }
        }
    }
}

extern "C" void kernel_launch(void* const* d_in, const int* in_sizes, int n_in,
                              void* d_out, int out_size) {
    const float* features = (const float*)d_in[0];
    const float* Wd       = (const float*)d_in[1];
    const float* bd       = (const float*)d_in[2];
    const float* Wg       = (const float*)d_in[3];
    const float* bg       = (const float*)d_in[4];
    const float* Wu       = (const float*)d_in[5];
    const float* bu       = (const float*)d_in[6];
    const int*   src      = (const int*)d_in[7];
    const int*   dst      = (const int*)d_in[8];
    float*       out      = (float*)d_out;

    const int n_nodes = in_sizes[0] / IN_DIM;
    const int n_edges = in_sizes[7];

    static float* p_h = nullptr; static float* p_agg = nullptr;
    static float* p_ns = nullptr; static float* p_nd = nullptr;
    static float* p_Wc = nullptr; static float* p_bc = nullptr;
    if (!p_h) {
        cudaGetSymbolAddress((void**)&p_h,   d_h);
        cudaGetSymbolAddress((void**)&p_agg, d_agg);
        cudaGetSymbolAddress((void**)&p_ns,  d_norm_src);
        cudaGetSymbolAddress((void**)&p_nd,  d_norm_dst);
        cudaGetSymbolAddress((void**)&p_Wc,  d_Wc);
        cudaGetSymbolAddress((void**)&p_bc,  d_bc);
    }

    const int nscan_blocks = (n_nodes + 1023) / 1024;

    zero_deg_kernel<<<(n_nodes + 255) / 256, 256>>>(n_nodes);
    degree_kernel<<<(n_edges + 255) / 256, 256>>>(src, dst, n_edges);
    norm_finalize_kernel<<<(n_nodes + 255) / 256, 256>>>(n_nodes);
    scan_block_kernel<<<nscan_blocks, 1024>>>(n_nodes);
    scan_sums_kernel<<<1, 32>>>(nscan_blocks);
    scan_add_kernel<<<(n_nodes + 255) / 256, 256>>>(n_nodes);
    csr_fill_kernel<<<(n_edges + 255) / 256, 256>>>(src, dst, n_edges);

    // h = (features @ Wd + bd) * norm_src   [N,128]
    {
        dim3 grid(OUT_DIM / 128, (n_nodes + 127) / 128);
        tf32_gemm<true><<<grid, 256>>>(features, Wd, bd, p_ns, p_h, n_nodes, OUT_DIM, IN_DIM);
    }

    combine_w_kernel<<<(OUT_DIM * IN_DIM + 255) / 256, 256>>>(Wg, bg, Wu, bu);

    gather_kernel<<<(n_nodes + 7) / 8, 256>>>(n_nodes);

    // out = (agg @ Wc) * norm_dst + bc     [N,768]
    {
        dim3 grid(IN_DIM / 128, (n_nodes + 127) / 128);
        tf32_gemm<false><<<grid, 256>>>(p_agg, p_Wc, p_bc, p_nd, out, n_nodes, IN_DIM, OUT_DIM);
    }
}

// round 5
// speedup vs baseline: 3.1886x; 1.1195x over previous
#include <cuda_runtime.h>
#include <cstdint>

#define N_NODES 100000
#define IN_DIM  768
#define OUT_DIM 128
#define MAX_EDGES 1600000

// -------- scratch (device globals; no allocation allowed) --------
__device__ float d_h[(size_t)N_NODES * OUT_DIM];
__device__ float d_agg[(size_t)N_NODES * OUT_DIM];
__device__ float d_norm_src[N_NODES];
__device__ float d_norm_dst[N_NODES];
__device__ float d_Wc[OUT_DIM * IN_DIM];             // Wg @ Wu   [128,768]
__device__ float d_bc[IN_DIM];                       // bg @ Wu + bu
__device__ int   d_outdeg[N_NODES];
__device__ int   d_indeg[N_NODES];
__device__ int   d_off[N_NODES + 1];
__device__ int   d_cursor[N_NODES];
__device__ int   d_blocksums[(N_NODES + 1023) / 1024 + 1];
__device__ int   d_edge_src[MAX_EDGES];

__device__ __forceinline__ uint32_t f2tf32(float f) {
    uint32_t u;
    asm("cvt.rna.tf32.f32 %0, %1;" : "=r"(u) : "f"(f));
    return u;
}

// -------- zero degree counters --------
__global__ void zero_deg_kernel(int n_nodes) {
    int i = blockIdx.x * blockDim.x + threadIdx.x;
    if (i < n_nodes) { d_outdeg[i] = 0; d_indeg[i] = 0; }
}

__global__ void degree_kernel(const int* __restrict__ src, const int* __restrict__ dst, int n_edges) {
    int i = blockIdx.x * blockDim.x + threadIdx.x;
    if (i < n_edges) {
        atomicAdd(&d_outdeg[src[i]], 1);
        atomicAdd(&d_indeg[dst[i]], 1);
    }
}

// -------- exclusive scan of indeg -> d_off --------
__global__ void scan_block_kernel(int n) {
    __shared__ int sh[1024];
    int gid = blockIdx.x * 1024 + threadIdx.x;
    int v = (gid < n) ? d_indeg[gid] : 0;
    sh[threadIdx.x] = v;
    __syncthreads();
    #pragma unroll
    for (int d = 1; d < 1024; d <<= 1) {
        int t = (threadIdx.x >= d) ? sh[threadIdx.x - d] : 0;
        __syncthreads();
        sh[threadIdx.x] += t;
        __syncthreads();
    }
    if (gid < n) d_off[gid] = sh[threadIdx.x] - v;
    if (threadIdx.x == 1023) d_blocksums[blockIdx.x] = sh[1023];
}

__global__ void scan_sums_kernel(int nb) {
    if (threadIdx.x == 0 && blockIdx.x == 0) {
        int acc = 0;
        for (int i = 0; i < nb; i++) { int v = d_blocksums[i]; d_blocksums[i] = acc; acc += v; }
    }
}

// scan finalize + norm computation + cursor zero (fused, all node-indexed)
__global__ void scan_add_norm_kernel(int n) {
    int gid = blockIdx.x * blockDim.x + threadIdx.x;
    if (gid < n) {
        d_off[gid] += d_blocksums[gid >> 10];
        d_cursor[gid] = 0;
        d_norm_src[gid] = rsqrtf(fmaxf((float)d_outdeg[gid], 1.0f));
        d_norm_dst[gid] = rsqrtf(fmaxf((float)d_indeg[gid], 1.0f));
    }
}

__global__ void csr_fill_kernel(const int* __restrict__ src, const int* __restrict__ dst, int n_edges) {
    int e = blockIdx.x * blockDim.x + threadIdx.x;
    if (e < n_edges) {
        int d = dst[e];
        int pos = d_off[d] + atomicAdd(&d_cursor[d], 1);
        d_edge_src[pos] = src[e];
    }
}

// -------- gather: agg[v] = sum_{e: dst=v} h[src[e]]  (one warp per node, ILP 8) --------
__global__ void gather_kernel(int n_nodes) {
    const int node = blockIdx.x * (blockDim.x >> 5) + (threadIdx.x >> 5);
    const int lane = threadIdx.x & 31;
    if (node >= n_nodes) return;
    const int beg = d_off[node];
    const int cnt = d_indeg[node];

    float4 acc = make_float4(0.f, 0.f, 0.f, 0.f);
    int j = 0;
    for (; j + 8 <= cnt; j += 8) {
        int s[8];
        #pragma unroll
        for (int u = 0; u < 8; u++) s[u] = d_edge_src[beg + j + u];
        float4 v[8];
        #pragma unroll
        for (int u = 0; u < 8; u++)
            v[u] = reinterpret_cast<const float4*>(d_h + (size_t)s[u] * OUT_DIM)[lane];
        #pragma unroll
        for (int u = 0; u < 8; u++) {
            acc.x += v[u].x; acc.y += v[u].y; acc.z += v[u].z; acc.w += v[u].w;
        }
    }
    for (; j + 4 <= cnt; j += 4) {
        int s[4];
        #pragma unroll
        for (int u = 0; u < 4; u++) s[u] = d_edge_src[beg + j + u];
        #pragma unroll
        for (int u = 0; u < 4; u++) {
            float4 v = reinterpret_cast<const float4*>(d_h + (size_t)s[u] * OUT_DIM)[lane];
            acc.x += v.x; acc.y += v.y; acc.z += v.z; acc.w += v.w;
        }
    }
    for (; j < cnt; j++) {
        const int s = d_edge_src[beg + j];
        float4 v = reinterpret_cast<const float4*>(d_h + (size_t)s * OUT_DIM)[lane];
        acc.x += v.x; acc.y += v.y; acc.z += v.z; acc.w += v.w;
    }
    reinterpret_cast<float4*>(d_agg + (size_t)node * OUT_DIM)[lane] = acc;
}

// -------- Wc = Wg @ Wu ; bc = bg @ Wu + bu --------
__global__ void combine_w_kernel(const float* __restrict__ Wg, const float* __restrict__ bg,
                                 const float* __restrict__ Wu, const float* __restrict__ bu) {
    int idx = blockIdx.x * blockDim.x + threadIdx.x;
    if (idx < OUT_DIM * IN_DIM) {
        int i = idx / IN_DIM;
        int j = idx % IN_DIM;
        float acc = 0.0f;
        #pragma unroll 8
        for (int k = 0; k < OUT_DIM; k++)
            acc += Wg[i * OUT_DIM + k] * Wu[k * IN_DIM + j];
        d_Wc[idx] = acc;
    }
    if (idx < IN_DIM) {
        float acc = bu[idx];
        #pragma unroll 8
        for (int k = 0; k < OUT_DIM; k++)
            acc += bg[k] * Wu[k * IN_DIM + idx];
        d_bc[idx] = acc;
    }
}

// ================= TF32 tensor-core GEMM, register-prefetch pipelined =================
// C[M,N] = epilogue(A[M,K] @ B[K,N])
// Block 128x128x16, 256 threads (8 warps, 2x4), warp tile 64x32.
#define SMEM_STRIDE 136

template<bool SCALE_AFTER_BIAS>
__global__ __launch_bounds__(256, 2)
void tf32_gemm(const float* __restrict__ A, const float* __restrict__ B,
               const float* __restrict__ bias, const float* __restrict__ rowscale,
               float* __restrict__ C, int M, int N, int K) {
    __shared__ float As[16 * SMEM_STRIDE];   // [k][m]
    __shared__ float Bs[16 * SMEM_STRIDE];   // [k][n]

    const int tid  = threadIdx.x;
    const int lane = tid & 31;
    const int wid  = tid >> 5;
    const int warp_m = (wid >> 2) * 64;
    const int warp_n = (wid & 3) * 32;

    const int brow = blockIdx.y * 128;
    const int bcol = blockIdx.x * 128;

    const int grp = lane >> 2;
    const int tig = lane & 3;

    // per-thread tile-load coordinates
    const int arow0 = tid >> 1;                // loads l=0: rows 0..127 (tid/2)
    const int acol0 = (tid & 1) << 3;          // not used; use scheme below
    (void)arow0; (void)acol0;

    float4 pa[2], pb[2];

    // load coords for l in {0,1}: A row = (tid + l*256)>>2, col4 = ((tid+l*256)&3)<<2
    auto load_tiles = [&](int k0) {
        #pragma unroll
        for (int l = 0; l < 2; l++) {
            const int idx  = tid + l * 256;
            const int arow = idx >> 2;
            const int acol = (idx & 3) << 2;
            const int gr = brow + arow;
            pa[l] = make_float4(0.f, 0.f, 0.f, 0.f);
            if (gr < M)
                pa[l] = *reinterpret_cast<const float4*>(A + (size_t)gr * K + k0 + acol);
            const int krow = idx >> 5;
            const int ncol = (idx & 31) << 2;
            pb[l] = *reinterpret_cast<const float4*>(B + (size_t)(k0 + krow) * N + bcol + ncol);
        }
    };
    auto store_tiles = [&]() {
        #pragma unroll
        for (int l = 0; l < 2; l++) {
            const int idx  = tid + l * 256;
            const int arow = idx >> 2;
            const int acol = (idx & 3) << 2;
            As[(acol + 0) * SMEM_STRIDE + arow] = __uint_as_float(f2tf32(pa[l].x));
            As[(acol + 1) * SMEM_STRIDE + arow] = __uint_as_float(f2tf32(pa[l].y));
            As[(acol + 2) * SMEM_STRIDE + arow] = __uint_as_float(f2tf32(pa[l].z));
            As[(acol + 3) * SMEM_STRIDE + arow] = __uint_as_float(f2tf32(pa[l].w));
            const int krow = idx >> 5;
            const int ncol = (idx & 31) << 2;
            float4 cv;
            cv.x = __uint_as_float(f2tf32(pb[l].x));
            cv.y = __uint_as_float(f2tf32(pb[l].y));
            cv.z = __uint_as_float(f2tf32(pb[l].z));
            cv.w = __uint_as_float(f2tf32(pb[l].w));
            *reinterpret_cast<float4*>(&Bs[krow * SMEM_STRIDE + ncol]) = cv;
        }
    };

    float acc[4][4][4];
    #pragma unroll
    for (int a = 0; a < 4; a++)
        #pragma unroll
        for (int b = 0; b < 4; b++)
            #pragma unroll
            for (int c = 0; c < 4; c++) acc[a][b][c] = 0.f;

    auto compute = [&]() {
        #pragma unroll
        for (int kk = 0; kk < 16; kk += 8) {
            uint32_t afr[4][4];
            #pragma unroll
            for (int mt = 0; mt < 4; mt++) {
                const int m0 = warp_m + mt * 16;
                afr[mt][0] = __float_as_uint(As[(kk + tig    ) * SMEM_STRIDE + m0 + grp    ]);
                afr[mt][1] = __float_as_uint(As[(kk + tig    ) * SMEM_STRIDE + m0 + grp + 8]);
                afr[mt][2] = __float_as_uint(As[(kk + tig + 4) * SMEM_STRIDE + m0 + grp    ]);
                afr[mt][3] = __float_as_uint(As[(kk + tig + 4) * SMEM_STRIDE + m0 + grp + 8]);
            }
            uint32_t bfr[4][2];
            #pragma unroll
            for (int nt = 0; nt < 4; nt++) {
                const int n0 = warp_n + nt * 8;
                bfr[nt][0] = __float_as_uint(Bs[(kk + tig    ) * SMEM_STRIDE + n0 + grp]);
                bfr[nt][1] = __float_as_uint(Bs[(kk + tig + 4) * SMEM_STRIDE + n0 + grp]);
            }
            #pragma unroll
            for (int mt = 0; mt < 4; mt++)
                #pragma unroll
                for (int nt = 0; nt < 4; nt++) {
                    asm volatile(
                        "mma.sync.aligned.m16n8k8.row.col.f32.tf32.tf32.f32 "
                        "{%0,%1,%2,%3}, {%4,%5,%6,%7}, {%8,%9}, {%0,%1,%2,%3};"
                        : "+f"(acc[mt][nt][0]), "+f"(acc[mt][nt][1]),
                          "+f"(acc[mt][nt][2]), "+f"(acc[mt][nt][3])
                        : "r"(afr[mt][0]), "r"(afr[mt][1]), "r"(afr[mt][2]), "r"(afr[mt][3]),
                          "r"(bfr[nt][0]), "r"(bfr[nt][1]));
                }
        }
    };

    // pipelined mainloop: prefetch next tile to regs while computing current
    load_tiles(0);
    store_tiles();
    __syncthreads();
    for (int k0 = 16; k0 < K; k0 += 16) {
        load_tiles(k0);      // global loads in flight during compute
        compute();
        __syncthreads();
        store_tiles();       // consumes arrived loads
        __syncthreads();
    }
    compute();

    // ---- epilogue ----
    #pragma unroll
    for (int mt = 0; mt < 4; mt++) {
        const int r0 = brow + warp_m + mt * 16 + grp;
        const int r1 = r0 + 8;
        const bool ok0 = (r0 < M);
        const bool ok1 = (r1 < M);
        const float s0 = ok0 ? rowscale[r0] : 0.f;
        const float s1 = ok1 ? rowscale[r1] : 0.f;
        #pragma unroll
        for (int nt = 0; nt < 4; nt++) {
            const int c = bcol + warp_n + nt * 8 + 2 * tig;
            const float bz0 = bias[c], bz1 = bias[c + 1];
            if (ok0) {
                float2 o;
                if (SCALE_AFTER_BIAS) {
                    o.x = (acc[mt][nt][0] + bz0) * s0;
                    o.y = (acc[mt][nt][1] + bz1) * s0;
                } else {
                    o.x = fmaf(acc[mt][nt][0], s0, bz0);
                    o.y = fmaf(acc[mt][nt][1], s0, bz1);
                }
                *reinterpret_cast<float2*>(C + (size_t)r0 * N + c) = o;
            }
            if (ok1) {
                float2 o;
                if (SCALE_AFTER_BIAS) {
                    o.x = (acc[mt][nt][2] + bz0) * s1;
                    o.y = (acc[mt][nt][3] + bz1) * s1;
                } else {
                    o.x = fmaf(acc[mt][nt][2], s1, bz0);
                    o.y = fmaf(acc[mt][nt][3], s1, bz1);
                }
                *reinterpret_cast<float2*>(C + (size_t)r1 * N + c) = o;
            }
        }
    }
}

extern "C" void kernel_launch(void* const* d_in, const int* in_sizes, int n_in,
                              void* d_out, int out_size) {
    const float* features = (const float*)d_in[0];
    const float* Wd       = (const float*)d_in[1];
    const float* bd       = (const float*)d_in[2];
    const float* Wg       = (const float*)d_in[3];
    const float* bg       = (const float*)d_in[4];
    const float* Wu       = (const float*)d_in[5];
    const float* bu       = (const float*)d_in[6];
    const int*   src      = (const int*)d_in[7];
    const int*   dst      = (const int*)d_in[8];
    float*       out      = (float*)d_out;

    const int n_nodes = in_sizes[0] / IN_DIM;
    const int n_edges = in_sizes[7];

    static float* p_h = nullptr; static float* p_agg = nullptr;
    static float* p_ns = nullptr; static float* p_nd = nullptr;
    static float* p_Wc = nullptr; static float* p_bc = nullptr;
    if (!p_h) {
        cudaGetSymbolAddress((void**)&p_h,   d_h);
        cudaGetSymbolAddress((void**)&p_agg, d_agg);
        cudaGetSymbolAddress((void**)&p_ns,  d_norm_src);
        cudaGetSymbolAddress((void**)&p_nd,  d_norm_dst);
        cudaGetSymbolAddress((void**)&p_Wc,  d_Wc);
        cudaGetSymbolAddress((void**)&p_bc,  d_bc);
    }

    const int nscan_blocks = (n_nodes + 1023) / 1024;

    zero_deg_kernel<<<(n_nodes + 255) / 256, 256>>>(n_nodes);
    degree_kernel<<<(n_edges + 255) / 256, 256>>>(src, dst, n_edges);
    scan_block_kernel<<<nscan_blocks, 1024>>>(n_nodes);
    scan_sums_kernel<<<1, 32>>>(nscan_blocks);
    scan_add_norm_kernel<<<(n_nodes + 255) / 256, 256>>>(n_nodes);
    csr_fill_kernel<<<(n_edges + 255) / 256, 256>>>(src, dst, n_edges);

    // h = (features @ Wd + bd) * norm_src   [N,128]
    {
        dim3 grid(OUT_DIM / 128, (n_nodes + 127) / 128);
        tf32_gemm<true><<<grid, 256>>>(features, Wd, bd, p_ns, p_h, n_nodes, OUT_DIM, IN_DIM);
    }

    combine_w_kernel<<<(OUT_DIM * IN_DIM + 255) / 256, 256>>>(Wg, bg, Wu, bu);

    gather_kernel<<<(n_nodes + 7) / 8, 256>>>(n_nodes);

    // out = (agg @ Wc) * norm_dst + bc     [N,768]
    {
        dim3 grid(IN_DIM / 128, (n_nodes + 127) / 128);
        tf32_gemm<false><<<grid, 256>>>(p_agg, p_Wc, p_bc, p_nd, out, n_nodes, IN_DIM, OUT_DIM);
    }
}

// round 6
// speedup vs baseline: 3.7178x; 1.1659x over previous
#include <cuda_runtime.h>
#include <cstdint>

#define N_NODES 100000
#define IN_DIM  768
#define OUT_DIM 128
#define MAX_EDGES 1600000

// -------- scratch (device globals; no allocation allowed) --------
__device__ float d_h[(size_t)N_NODES * OUT_DIM];
__device__ float d_agg[(size_t)N_NODES * OUT_DIM];
__device__ float d_norm_src[N_NODES];
__device__ float d_norm_dst[N_NODES];
__device__ float d_Wc[OUT_DIM * IN_DIM];             // tf32-rounded Wg @ Wu   [128,768]
__device__ float d_bc[IN_DIM];                       // bg @ Wu + bu (fp32)
__device__ float d_Wdr[IN_DIM * OUT_DIM];            // tf32-rounded Wd [768,128]
__device__ int   d_outdeg[N_NODES];
__device__ int   d_indeg[N_NODES];
__device__ int   d_off[N_NODES + 1];
__device__ int   d_cursor[N_NODES];
__device__ int   d_blocksums[(N_NODES + 1023) / 1024 + 1];
__device__ int   d_edge_src[MAX_EDGES];

__device__ __forceinline__ uint32_t f2tf32(float f) {
    uint32_t u;
    asm("cvt.rna.tf32.f32 %0, %1;" : "=r"(u) : "f"(f));
    return u;
}

// -------- zero degree counters --------
__global__ void zero_deg_kernel(int n_nodes) {
    int i = blockIdx.x * blockDim.x + threadIdx.x;
    if (i < n_nodes) { d_outdeg[i] = 0; d_indeg[i] = 0; }
}

__global__ void degree_kernel(const int* __restrict__ src, const int* __restrict__ dst, int n_edges) {
    int i = blockIdx.x * blockDim.x + threadIdx.x;
    if (i < n_edges) {
        atomicAdd(&d_outdeg[src[i]], 1);
        atomicAdd(&d_indeg[dst[i]], 1);
    }
}

__global__ void norm_kernel(int n) {
    int i = blockIdx.x * blockDim.x + threadIdx.x;
    if (i < n) {
        d_norm_src[i] = rsqrtf(fmaxf((float)d_outdeg[i], 1.0f));
        d_norm_dst[i] = rsqrtf(fmaxf((float)d_indeg[i], 1.0f));
    }
}

// -------- Wd pre-round to tf32 --------
__global__ void wd_round_kernel(const float* __restrict__ Wd) {
    int i = blockIdx.x * blockDim.x + threadIdx.x;
    if (i < IN_DIM * OUT_DIM) d_Wdr[i] = __uint_as_float(f2tf32(Wd[i]));
}

// -------- exclusive scan of indeg -> d_off --------
__global__ void scan_block_kernel(int n) {
    __shared__ int sh[1024];
    int gid = blockIdx.x * 1024 + threadIdx.x;
    int v = (gid < n) ? d_indeg[gid] : 0;
    sh[threadIdx.x] = v;
    __syncthreads();
    #pragma unroll
    for (int d = 1; d < 1024; d <<= 1) {
        int t = (threadIdx.x >= d) ? sh[threadIdx.x - d] : 0;
        __syncthreads();
        sh[threadIdx.x] += t;
        __syncthreads();
    }
    if (gid < n) d_off[gid] = sh[threadIdx.x] - v;
    if (threadIdx.x == 1023) d_blocksums[blockIdx.x] = sh[1023];
}

__global__ void scan_sums_kernel(int nb) {
    if (threadIdx.x == 0 && blockIdx.x == 0) {
        int acc = 0;
        for (int i = 0; i < nb; i++) { int v = d_blocksums[i]; d_blocksums[i] = acc; acc += v; }
    }
}

__global__ void scan_add_kernel(int n) {
    int gid = blockIdx.x * blockDim.x + threadIdx.x;
    if (gid < n) {
        d_off[gid] += d_blocksums[gid >> 10];
        d_cursor[gid] = 0;
    }
}

__global__ void csr_fill_kernel(const int* __restrict__ src, const int* __restrict__ dst, int n_edges) {
    int e = blockIdx.x * blockDim.x + threadIdx.x;
    if (e < n_edges) {
        int d = dst[e];
        int pos = d_off[d] + atomicAdd(&d_cursor[d], 1);
        d_edge_src[pos] = src[e];
    }
}

// -------- gather: agg[v] = sum_{e: dst=v} h[src[e]]  (one warp/node, ILP 8, tf32-rounded out) --------
__global__ void gather_kernel(int n_nodes) {
    const int node = blockIdx.x * (blockDim.x >> 5) + (threadIdx.x >> 5);
    const int lane = threadIdx.x & 31;
    if (node >= n_nodes) return;
    const int beg = d_off[node];
    const int cnt = d_indeg[node];

    float4 acc = make_float4(0.f, 0.f, 0.f, 0.f);
    int j = 0;
    for (; j + 8 <= cnt; j += 8) {
        int s[8];
        #pragma unroll
        for (int u = 0; u < 8; u++) s[u] = d_edge_src[beg + j + u];
        float4 v[8];
        #pragma unroll
        for (int u = 0; u < 8; u++)
            v[u] = reinterpret_cast<const float4*>(d_h + (size_t)s[u] * OUT_DIM)[lane];
        #pragma unroll
        for (int u = 0; u < 8; u++) {
            acc.x += v[u].x; acc.y += v[u].y; acc.z += v[u].z; acc.w += v[u].w;
        }
    }
    for (; j < cnt; j++) {
        const int s = d_edge_src[beg + j];
        float4 v = reinterpret_cast<const float4*>(d_h + (size_t)s * OUT_DIM)[lane];
        acc.x += v.x; acc.y += v.y; acc.z += v.z; acc.w += v.w;
    }
    float4 o;
    o.x = __uint_as_float(f2tf32(acc.x));
    o.y = __uint_as_float(f2tf32(acc.y));
    o.z = __uint_as_float(f2tf32(acc.z));
    o.w = __uint_as_float(f2tf32(acc.w));
    reinterpret_cast<float4*>(d_agg + (size_t)node * OUT_DIM)[lane] = o;
}

// -------- Wc = tf32(Wg @ Wu) ; bc = bg @ Wu + bu --------
__global__ void combine_w_kernel(const float* __restrict__ Wg, const float* __restrict__ bg,
                                 const float* __restrict__ Wu, const float* __restrict__ bu) {
    int idx = blockIdx.x * blockDim.x + threadIdx.x;
    if (idx < OUT_DIM * IN_DIM) {
        int i = idx / IN_DIM;
        int j = idx % IN_DIM;
        float acc = 0.0f;
        #pragma unroll 8
        for (int k = 0; k < OUT_DIM; k++)
            acc += Wg[i * OUT_DIM + k] * Wu[k * IN_DIM + j];
        d_Wc[idx] = __uint_as_float(f2tf32(acc));
    }
    if (idx < IN_DIM) {
        float acc = bu[idx];
        #pragma unroll 8
        for (int k = 0; k < OUT_DIM; k++)
            acc += bg[k] * Wu[k * IN_DIM + idx];
        d_bc[idx] = acc;
    }
}

// ================= TF32 tensor-core GEMM, cp.async double-buffered =================
// Block 128x128x16, 256 threads (8 warps 2x4), warp tile 64x32.
// As [m][k] stride 20 (conflict-free frag LDS), Bs [k][n] stride 136.
#define SA 20
#define SB 136

template<bool SCALE_AFTER_BIAS, bool CVT_A>
__global__ __launch_bounds__(256, 2)
void tf32_gemm(const float* __restrict__ A, const float* __restrict__ B,
               const float* __restrict__ bias, const float* __restrict__ rowscale,
               float* __restrict__ C, int M, int N, int K) {
    __shared__ float As[2 * 128 * SA];
    __shared__ float Bs[2 * 16 * SB];

    const int tid  = threadIdx.x;
    const int lane = tid & 31;
    const int wid  = tid >> 5;
    const int warp_m = (wid >> 2) * 64;
    const int warp_n = (wid & 3) * 32;

    const int brow = blockIdx.y * 128;
    const int bcol = blockIdx.x * 128;

    const int grp = lane >> 2;
    const int tig = lane & 3;

    // cp.async per-thread coords (2 chunks each for A and B)
    const int a_row0 = tid >> 2;             // + l*64
    const int a_kc   = (tid & 3) << 2;
    const int b_row0 = tid >> 5;             // + l*8
    const int b_nc   = (tid & 31) << 2;

    auto issue = [&](int buf, int k0) {
        float* as = As + buf * 128 * SA;
        float* bs = Bs + buf * 16 * SB;
        #pragma unroll
        for (int l = 0; l < 2; l++) {
            const int arow = a_row0 + l * 64;
            const float* gsrc = A + (size_t)(brow + arow) * K + k0 + a_kc;
            uint32_t sdst = (uint32_t)__cvta_generic_to_shared(as + arow * SA + a_kc);
            int vbytes = (brow + arow < M) ? 16 : 0;
            asm volatile("cp.async.cg.shared.global [%0], [%1], 16, %2;"
                         :: "r"(sdst), "l"(gsrc), "r"(vbytes));
            const int krow = b_row0 + l * 8;
            const float* gsb = B + (size_t)(k0 + krow) * N + bcol + b_nc;
            uint32_t sdb = (uint32_t)__cvta_generic_to_shared(bs + krow * SB + b_nc);
            asm volatile("cp.async.cg.shared.global [%0], [%1], 16;"
                         :: "r"(sdb), "l"(gsb));
        }
        asm volatile("cp.async.commit_group;");
    };

    float acc[4][4][4];
    #pragma unroll
    for (int a = 0; a < 4; a++)
        #pragma unroll
        for (int b = 0; b < 4; b++)
            #pragma unroll
            for (int c = 0; c < 4; c++) acc[a][b][c] = 0.f;

    auto compute = [&](int buf) {
        const float* as = As + buf * 128 * SA;
        const float* bs = Bs + buf * 16 * SB;
        #pragma unroll
        for (int kk = 0; kk < 16; kk += 8) {
            uint32_t afr[4][4];
            #pragma unroll
            for (int mt = 0; mt < 4; mt++) {
                const int m0 = warp_m + mt * 16;
                float a0 = as[(m0 + grp    ) * SA + kk + tig    ];
                float a1 = as[(m0 + grp + 8) * SA + kk + tig    ];
                float a2 = as[(m0 + grp    ) * SA + kk + tig + 4];
                float a3 = as[(m0 + grp + 8) * SA + kk + tig + 4];
                if (CVT_A) {
                    afr[mt][0] = f2tf32(a0); afr[mt][1] = f2tf32(a1);
                    afr[mt][2] = f2tf32(a2); afr[mt][3] = f2tf32(a3);
                } else {
                    afr[mt][0] = __float_as_uint(a0); afr[mt][1] = __float_as_uint(a1);
                    afr[mt][2] = __float_as_uint(a2); afr[mt][3] = __float_as_uint(a3);
                }
            }
            uint32_t bfr[4][2];
            #pragma unroll
            for (int nt = 0; nt < 4; nt++) {
                const int n0 = warp_n + nt * 8;
                bfr[nt][0] = __float_as_uint(bs[(kk + tig    ) * SB + n0 + grp]);
                bfr[nt][1] = __float_as_uint(bs[(kk + tig + 4) * SB + n0 + grp]);
            }
            #pragma unroll
            for (int mt = 0; mt < 4; mt++)
                #pragma unroll
                for (int nt = 0; nt < 4; nt++) {
                    asm volatile(
                        "mma.sync.aligned.m16n8k8.row.col.f32.tf32.tf32.f32 "
                        "{%0,%1,%2,%3}, {%4,%5,%6,%7}, {%8,%9}, {%0,%1,%2,%3};"
                        : "+f"(acc[mt][nt][0]), "+f"(acc[mt][nt][1]),
                          "+f"(acc[mt][nt][2]), "+f"(acc[mt][nt][3])
                        : "r"(afr[mt][0]), "r"(afr[mt][1]), "r"(afr[mt][2]), "r"(afr[mt][3]),
                          "r"(bfr[nt][0]), "r"(bfr[nt][1]));
                }
        }
    };

    const int nk = K / 16;
    issue(0, 0);
    int buf = 0;
    for (int t = 0; t < nk; t++) {
        asm volatile("cp.async.wait_group 0;");
        __syncthreads();
        if (t + 1 < nk) issue(buf ^ 1, (t + 1) * 16);
        compute(buf);
        buf ^= 1;
    }

    // ---- epilogue ----
    #pragma unroll
    for (int mt = 0; mt < 4; mt++) {
        const int r0 = brow + warp_m + mt * 16 + grp;
        const int r1 = r0 + 8;
        const bool ok0 = (r0 < M);
        const bool ok1 = (r1 < M);
        const float s0 = ok0 ? rowscale[r0] : 0.f;
        const float s1 = ok1 ? rowscale[r1] : 0.f;
        #pragma unroll
        for (int nt = 0; nt < 4; nt++) {
            const int c = bcol + warp_n + nt * 8 + 2 * tig;
            const float bz0 = bias[c], bz1 = bias[c + 1];
            if (ok0) {
                float2 o;
                if (SCALE_AFTER_BIAS) {
                    o.x = (acc[mt][nt][0] + bz0) * s0;
                    o.y = (acc[mt][nt][1] + bz1) * s0;
                } else {
                    o.x = fmaf(acc[mt][nt][0], s0, bz0);
                    o.y = fmaf(acc[mt][nt][1], s0, bz1);
                }
                *reinterpret_cast<float2*>(C + (size_t)r0 * N + c) = o;
            }
            if (ok1) {
                float2 o;
                if (SCALE_AFTER_BIAS) {
                    o.x = (acc[mt][nt][2] + bz0) * s1;
                    o.y = (acc[mt][nt][3] + bz1) * s1;
                } else {
                    o.x = fmaf(acc[mt][nt][2], s1, bz0);
                    o.y = fmaf(acc[mt][nt][3], s1, bz1);
                }
                *reinterpret_cast<float2*>(C + (size_t)r1 * N + c) = o;
            }
        }
    }
}

extern "C" void kernel_launch(void* const* d_in, const int* in_sizes, int n_in,
                              void* d_out, int out_size) {
    const float* features = (const float*)d_in[0];
    const float* Wd       = (const float*)d_in[1];
    const float* bd       = (const float*)d_in[2];
    const float* Wg       = (const float*)d_in[3];
    const float* bg       = (const float*)d_in[4];
    const float* Wu       = (const float*)d_in[5];
    const float* bu       = (const float*)d_in[6];
    const int*   src      = (const int*)d_in[7];
    const int*   dst      = (const int*)d_in[8];
    float*       out      = (float*)d_out;

    const int n_nodes = in_sizes[0] / IN_DIM;
    const int n_edges = in_sizes[7];

    static float* p_h = nullptr; static float* p_agg = nullptr;
    static float* p_ns = nullptr; static float* p_nd = nullptr;
    static float* p_Wc = nullptr; static float* p_bc = nullptr;
    static float* p_Wdr = nullptr;
    static cudaStream_t s1;
    static cudaEvent_t ev_deg, ev_csr;
    if (!p_h) {
        cudaGetSymbolAddress((void**)&p_h,   d_h);
        cudaGetSymbolAddress((void**)&p_agg, d_agg);
        cudaGetSymbolAddress((void**)&p_ns,  d_norm_src);
        cudaGetSymbolAddress((void**)&p_nd,  d_norm_dst);
        cudaGetSymbolAddress((void**)&p_Wc,  d_Wc);
        cudaGetSymbolAddress((void**)&p_bc,  d_bc);
        cudaGetSymbolAddress((void**)&p_Wdr, d_Wdr);
        cudaStreamCreateWithFlags(&s1, cudaStreamNonBlocking);
        cudaEventCreateWithFlags(&ev_deg, cudaEventDisableTiming);
        cudaEventCreateWithFlags(&ev_csr, cudaEventDisableTiming);
    }

    const int nscan_blocks = (n_nodes + 1023) / 1024;

    // main stream: degrees -> norms, Wd round
    zero_deg_kernel<<<(n_nodes + 255) / 256, 256>>>(n_nodes);
    degree_kernel<<<(n_edges + 255) / 256, 256>>>(src, dst, n_edges);
    norm_kernel<<<(n_nodes + 255) / 256, 256>>>(n_nodes);
    wd_round_kernel<<<(IN_DIM * OUT_DIM + 255) / 256, 256>>>(Wd);
    cudaEventRecord(ev_deg, 0);

    // side stream: CSR build + combine_w, concurrent with GEMM1
    cudaStreamWaitEvent(s1, ev_deg, 0);
    scan_block_kernel<<<nscan_blocks, 1024, 0, s1>>>(n_nodes);
    scan_sums_kernel<<<1, 32, 0, s1>>>(nscan_blocks);
    scan_add_kernel<<<(n_nodes + 255) / 256, 256, 0, s1>>>(n_nodes);
    csr_fill_kernel<<<(n_edges + 255) / 256, 256, 0, s1>>>(src, dst, n_edges);
    combine_w_kernel<<<(OUT_DIM * IN_DIM + 255) / 256, 256, 0, s1>>>(Wg, bg, Wu, bu);
    cudaEventRecord(ev_csr, s1);

    // main stream: GEMM1  h = (features @ Wd + bd) * norm_src
    {
        dim3 grid(OUT_DIM / 128, (n_nodes + 127) / 128);
        tf32_gemm<true, true><<<grid, 256>>>(features, p_Wdr, bd, p_ns, p_h, n_nodes, OUT_DIM, IN_DIM);
    }

    // join, then gather + GEMM2
    cudaStreamWaitEvent(0, ev_csr, 0);
    gather_kernel<<<(n_nodes + 7) / 8, 256>>>(n_nodes);
    {
        dim3 grid(IN_DIM / 128, (n_nodes + 127) / 128);
        tf32_gemm<false, false><<<grid, 256>>>(p_agg, p_Wc, p_bc, p_nd, out, n_nodes, IN_DIM, OUT_DIM);
    }
}